// round 1
// baseline (speedup 1.0000x reference)
#include <cuda_runtime.h>
#include <float.h>
#include <math.h>

#define NN 8192
#define DD 128
#define CC 7
#define KNN 5
#define EPSF 1e-6f

#define BI 64
#define BJ 128
#define KT 16
#define JSPLIT 2
#define RTILES (NN / BI)   // 128 row tiles

// ---------------- device scratch (no allocations allowed) ----------------
__device__ float  g_rn[NN];                       // ||x_i+eps||^2 folded
__device__ float  g_cn[NN];                       // ||x_j||^2 - 2 eps sum(x_j)
__device__ float  g_part5[JSPLIT][NN][KNN];       // per-split top-5 d2
__device__ double g_accCE;
__device__ double g_accPair;

// ---------------- init ----------------
__global__ void k_init() {
    g_accCE = 0.0;
    g_accPair = 0.0;
}

// ---------------- row norms / sums ----------------
__global__ void k_norms(const float* __restrict__ x) {
    int row  = blockIdx.x * 8 + (threadIdx.x >> 5);
    int lane = threadIdx.x & 31;
    float4 v = reinterpret_cast<const float4*>(x + (size_t)row * DD)[lane]; // 32 float4 = 128 floats
    float s  = v.x + v.y + v.z + v.w;
    float n2 = v.x * v.x + v.y * v.y + v.z * v.z + v.w * v.w;
#pragma unroll
    for (int o = 16; o > 0; o >>= 1) {
        s  += __shfl_xor_sync(0xffffffffu, s, o);
        n2 += __shfl_xor_sync(0xffffffffu, n2, o);
    }
    if (lane == 0) {
        g_rn[row] = n2 + 2.0f * EPSF * s + (float)DD * EPSF * EPSF;
        g_cn[row] = n2 - 2.0f * EPSF * s;
    }
}

// ---------------- cross entropy ----------------
__global__ void k_ce(const float* __restrict__ sc, const int* __restrict__ tg) {
    int i = blockIdx.x * blockDim.x + threadIdx.x;   // exactly NN threads
    const float* s = sc + (size_t)i * CC;
    float m = s[0];
#pragma unroll
    for (int c = 1; c < CC; c++) m = fmaxf(m, s[c]);
    float sum = 0.f;
#pragma unroll
    for (int c = 0; c < CC; c++) sum += expf(s[c] - m);
    float ce = m + logf(sum) - s[tg[i]];

    __shared__ double sh[256];
    sh[threadIdx.x] = (double)ce;
    __syncthreads();
#pragma unroll
    for (int o = 128; o > 0; o >>= 1) {
        if (threadIdx.x < o) sh[threadIdx.x] += sh[threadIdx.x + o];
        __syncthreads();
    }
    if (threadIdx.x == 0) atomicAdd(&g_accCE, sh[0]);
}

// ---------------- fused Gram tile + streaming top-5 ----------------
__global__ void __launch_bounds__(256, 2)
k_dist(const float* __restrict__ x, const int* __restrict__ tgt) {
    __shared__ __align__(16) float As[KT][BI];        // 4 KB, K-major
    __shared__ __align__(16) float Bs[KT][BJ];        // 8 KB, K-major
    __shared__ float Cs[BI][BJ + 1];                  // 33 KB, padded
    __shared__ int   tgs[BJ];
    __shared__ float cns[BJ];

    int bid   = blockIdx.x;
    int rt    = bid & (RTILES - 1);
    int split = bid >> 7;            // bid / RTILES
    int rowBase = rt * BI;
    int tid = threadIdx.x;
    int tx = tid & 15;               // 16 col-groups of 8
    int ty = tid >> 4;               // 16 row-groups of 4
    int jBegin = split * (NN / JSPLIT);
    int jEnd   = jBegin + (NN / JSPLIT);

    // per-row state (threads 0..63 own one row each)
    float t5[KNN];
    float th = FLT_MAX;
    float rni = 0.f;
    int tgi = -1, iglob = -1;
    if (tid < BI) {
        iglob = rowBase + tid;
        rni = g_rn[iglob];
        tgi = tgt[iglob];
#pragma unroll
        for (int k = 0; k < KNN; k++) t5[k] = FLT_MAX;
    }

    for (int jt = jBegin; jt < jEnd; jt += BJ) {
        if (tid < BJ) {
            tgs[tid] = tgt[jt + tid];
            cns[tid] = g_cn[jt + tid];
        }
        float acc[4][8];
#pragma unroll
        for (int r = 0; r < 4; r++)
#pragma unroll
            for (int c = 0; c < 8; c++) acc[r][c] = 0.f;

        for (int kc = 0; kc < DD; kc += KT) {
            // load A chunk (64x16) transposed: 1 float4 per thread
            {
                int r  = tid >> 2;
                int d4 = (tid & 3) << 2;
                float4 va = *reinterpret_cast<const float4*>(
                    x + (size_t)(rowBase + r) * DD + kc + d4);
                As[d4 + 0][r] = va.x; As[d4 + 1][r] = va.y;
                As[d4 + 2][r] = va.z; As[d4 + 3][r] = va.w;
            }
            // load B chunk (128x16) transposed: 2 float4 per thread
#pragma unroll
            for (int h = 0; h < 2; h++) {
                int f  = tid + h * 256;
                int j  = f >> 2;
                int d4 = (f & 3) << 2;
                float4 vb = *reinterpret_cast<const float4*>(
                    x + (size_t)(jt + j) * DD + kc + d4);
                Bs[d4 + 0][j] = vb.x; Bs[d4 + 1][j] = vb.y;
                Bs[d4 + 2][j] = vb.z; Bs[d4 + 3][j] = vb.w;
            }
            __syncthreads();

#pragma unroll
            for (int k = 0; k < KT; k++) {
                float a[4], b[8];
                *reinterpret_cast<float4*>(a)     = *reinterpret_cast<float4*>(&As[k][ty << 2]);
                *reinterpret_cast<float4*>(b)     = *reinterpret_cast<float4*>(&Bs[k][tx << 3]);
                *reinterpret_cast<float4*>(b + 4) = *reinterpret_cast<float4*>(&Bs[k][(tx << 3) + 4]);
#pragma unroll
                for (int r = 0; r < 4; r++)
#pragma unroll
                    for (int c = 0; c < 8; c++) acc[r][c] = fmaf(a[r], b[c], acc[r][c]);
            }
            __syncthreads();
        }

        // stage dot products
#pragma unroll
        for (int r = 0; r < 4; r++)
#pragma unroll
            for (int c = 0; c < 8; c++)
                Cs[(ty << 2) + r][(tx << 3) + c] = acc[r][c];
        __syncthreads();

        // streaming top-5 (row-owner threads)
        if (tid < BI) {
            for (int jj = 0; jj < BJ; jj++) {
                if (tgs[jj] != tgi) continue;
                int j = jt + jj;
                float d2 = rni + cns[jj] - 2.0f * Cs[tid][jj];
                if (d2 < th && j != iglob) {
                    int mi = 0; float mv = t5[0];
#pragma unroll
                    for (int k = 1; k < KNN; k++)
                        if (t5[k] > mv) { mv = t5[k]; mi = k; }
#pragma unroll
                    for (int k = 0; k < KNN; k++)
                        if (k == mi) t5[k] = d2;
                    th = t5[0];
#pragma unroll
                    for (int k = 1; k < KNN; k++) th = fmaxf(th, t5[k]);
                }
            }
        }
        __syncthreads();
    }

    if (tid < BI) {
#pragma unroll
        for (int k = 0; k < KNN; k++) g_part5[split][iglob][k] = t5[k];
    }
}

// ---------------- merge splits + pair sum ----------------
__global__ void k_merge() {
    int i = blockIdx.x * blockDim.x + threadIdx.x;   // exactly NN threads
    float v[JSPLIT * KNN];
#pragma unroll
    for (int sp = 0; sp < JSPLIT; sp++)
#pragma unroll
        for (int k = 0; k < KNN; k++) v[sp * KNN + k] = g_part5[sp][i][k];

    float sum = 0.f;
#pragma unroll
    for (int sel = 0; sel < KNN; sel++) {
        float mv = v[0]; int mi = 0;
#pragma unroll
        for (int k = 1; k < JSPLIT * KNN; k++)
            if (v[k] < mv) { mv = v[k]; mi = k; }
        if (mv < 1e37f) sum += mv;          // skip "fewer than K neighbors" sentinels
#pragma unroll
        for (int k = 0; k < JSPLIT * KNN; k++)
            if (k == mi) v[k] = FLT_MAX;
    }

    __shared__ double sh[256];
    sh[threadIdx.x] = (double)sum / (double)DD;   // sum of per-pair MSE
    __syncthreads();
#pragma unroll
    for (int o = 128; o > 0; o >>= 1) {
        if (threadIdx.x < o) sh[threadIdx.x] += sh[threadIdx.x + o];
        __syncthreads();
    }
    if (threadIdx.x == 0) atomicAdd(&g_accPair, sh[0]);
}

// ---------------- finalize ----------------
__global__ void k_final(float* out) {
    out[0] = (float)(g_accCE / (double)NN + (0.5 / (double)KNN) * g_accPair);
}

// ---------------- launch ----------------
extern "C" void kernel_launch(void* const* d_in, const int* in_sizes, int n_in,
                              void* d_out, int out_size) {
    // identify inputs by element count for robustness
    const float* x  = nullptr;
    const float* sc = nullptr;
    const int*   tg = nullptr;
    for (int i = 0; i < n_in; i++) {
        if (in_sizes[i] == NN * DD)      x  = (const float*)d_in[i];
        else if (in_sizes[i] == NN * CC) sc = (const float*)d_in[i];
        else if (in_sizes[i] == NN)      tg = (const int*)d_in[i];
    }
    float* out = (float*)d_out;

    k_init<<<1, 1>>>();
    k_norms<<<NN / 8, 256>>>(x);
    k_ce<<<NN / 256, 256>>>(sc, tg);
    k_dist<<<RTILES * JSPLIT, 256>>>(x, tg);
    k_merge<<<NN / 256, 256>>>();
    k_final<<<1, 1>>>(out);
}

// round 3
// speedup vs baseline: 2.5511x; 2.5511x over previous
#include <cuda_runtime.h>
#include <cuda_bf16.h>
#include <float.h>
#include <math.h>
#include <stdint.h>

#define NN 8192
#define DD 128
#define CC 7
#define KNN 5
#define EPSF 1e-6f

#define BM 128
#define BN 64
#define JHALVES 2
#define JTILES (NN / JHALVES / BN)     // 64 j-tiles per CTA
#define ITILES (NN / BM)               // 64 i-tiles

// padded strides (bytes)
#define ASTRIDE 272                    // 128 bf16 = 256B + 16B pad
#define CSTRIDE 70                     // floats (280B, 8B aligned, low conflict)

// ---------------- smem map (bytes) ----------------
#define SM_TG   0                       // int  [4096]
#define SM_CN   16384                   // float[4096]
#define SM_AH   32768                   // 128 * 272
#define SM_AL   67584
#define SM_B    102400                  // 2 stages * 34816 (hi 17408 + lo 17408)
#define SM_BSTG 34816
#define SM_BLO  17408
#define SM_C    172032                  // 128 * 70 * 4
#define SM_TOTAL 207872

// ---------------- device scratch ----------------
__device__ __nv_bfloat16 g_hi[NN * DD];
__device__ __nv_bfloat16 g_lo[NN * DD];
__device__ float  g_rn[NN];
__device__ float  g_cn[NN];
__device__ float  g_part5[JHALVES][NN][KNN];
__device__ double g_accCE;
__device__ double g_accPair;

// ---------------- PTX helpers ----------------
__device__ __forceinline__ uint32_t smem_u32(const void* p) {
    uint32_t a;
    asm("{ .reg .u64 t; cvta.to.shared.u64 t, %1; cvt.u32.u64 %0, t; }" : "=r"(a) : "l"(p));
    return a;
}
__device__ __forceinline__ void cp16(uint32_t s, const void* g) {
    asm volatile("cp.async.cg.shared.global [%0], [%1], 16;" :: "r"(s), "l"(g));
}
#define CP_COMMIT() asm volatile("cp.async.commit_group;" ::: "memory")
#define CP_WAIT1()  asm volatile("cp.async.wait_group 1;" ::: "memory")

__device__ __forceinline__ void ldsm4(uint32_t* r, uint32_t a) {
    asm volatile("ldmatrix.sync.aligned.m8n8.x4.shared.b16 {%0,%1,%2,%3}, [%4];"
                 : "=r"(r[0]), "=r"(r[1]), "=r"(r[2]), "=r"(r[3]) : "r"(a));
}
__device__ __forceinline__ void ldsm2(uint32_t* r, uint32_t a) {
    asm volatile("ldmatrix.sync.aligned.m8n8.x2.shared.b16 {%0,%1}, [%2];"
                 : "=r"(r[0]), "=r"(r[1]) : "r"(a));
}
__device__ __forceinline__ void mma_bf16(float* c, const uint32_t* a, const uint32_t* b) {
    asm volatile("mma.sync.aligned.m16n8k16.row.col.f32.bf16.bf16.f32 "
                 "{%0,%1,%2,%3}, {%4,%5,%6,%7}, {%8,%9}, {%0,%1,%2,%3};"
                 : "+f"(c[0]), "+f"(c[1]), "+f"(c[2]), "+f"(c[3])
                 : "r"(a[0]), "r"(a[1]), "r"(a[2]), "r"(a[3]), "r"(b[0]), "r"(b[1]));
}

// ---------------- small kernels ----------------
__global__ void k_init() { g_accCE = 0.0; g_accPair = 0.0; }

__global__ void k_convert(const float* __restrict__ x) {
    int idx = blockIdx.x * blockDim.x + threadIdx.x;      // NN*DD/4 threads
    float4 v = reinterpret_cast<const float4*>(x)[idx];
    __nv_bfloat16 h0 = __float2bfloat16(v.x), h1 = __float2bfloat16(v.y);
    __nv_bfloat16 h2 = __float2bfloat16(v.z), h3 = __float2bfloat16(v.w);
    __nv_bfloat162 hh0 = {h0, h1}, hh1 = {h2, h3};
    __nv_bfloat162 ll0 = {__float2bfloat16(v.x - __bfloat162float(h0)),
                          __float2bfloat16(v.y - __bfloat162float(h1))};
    __nv_bfloat162 ll1 = {__float2bfloat16(v.z - __bfloat162float(h2)),
                          __float2bfloat16(v.w - __bfloat162float(h3))};
    reinterpret_cast<__nv_bfloat162*>(g_hi)[idx * 2]     = hh0;
    reinterpret_cast<__nv_bfloat162*>(g_hi)[idx * 2 + 1] = hh1;
    reinterpret_cast<__nv_bfloat162*>(g_lo)[idx * 2]     = ll0;
    reinterpret_cast<__nv_bfloat162*>(g_lo)[idx * 2 + 1] = ll1;
}

__global__ void k_norms(const float* __restrict__ x) {
    int row  = blockIdx.x * 8 + (threadIdx.x >> 5);
    int lane = threadIdx.x & 31;
    float4 v = reinterpret_cast<const float4*>(x + (size_t)row * DD)[lane];
    float s  = v.x + v.y + v.z + v.w;
    float n2 = v.x * v.x + v.y * v.y + v.z * v.z + v.w * v.w;
#pragma unroll
    for (int o = 16; o > 0; o >>= 1) {
        s  += __shfl_xor_sync(0xffffffffu, s, o);
        n2 += __shfl_xor_sync(0xffffffffu, n2, o);
    }
    if (lane == 0) {
        g_rn[row] = n2 + 2.0f * EPSF * s + (float)DD * EPSF * EPSF;
        g_cn[row] = n2 - 2.0f * EPSF * s;
    }
}

__global__ void k_ce(const float* __restrict__ sc, const int* __restrict__ tg) {
    int i = blockIdx.x * blockDim.x + threadIdx.x;
    const float* s = sc + (size_t)i * CC;
    float m = s[0];
#pragma unroll
    for (int c = 1; c < CC; c++) m = fmaxf(m, s[c]);
    float sum = 0.f;
#pragma unroll
    for (int c = 0; c < CC; c++) sum += expf(s[c] - m);
    float ce = m + logf(sum) - s[tg[i]];

    __shared__ double sh[256];
    sh[threadIdx.x] = (double)ce;
    __syncthreads();
#pragma unroll
    for (int o = 128; o > 0; o >>= 1) {
        if (threadIdx.x < o) sh[threadIdx.x] += sh[threadIdx.x + o];
        __syncthreads();
    }
    if (threadIdx.x == 0) atomicAdd(&g_accCE, sh[0]);
}

// ---------------- fused bf16 mma.sync GEMM + streaming top-5 ----------------
__global__ void __launch_bounds__(256, 1)
k_dist(const int* __restrict__ tgt) {
    extern __shared__ char smem[];
    uint32_t smb = smem_u32(smem);
    int tid  = threadIdx.x;
    int lane = tid & 31;
    int w    = tid >> 5;
    int wm   = w >> 1;          // 0..3 : warp row block (32 rows)
    int wn   = w & 1;           // 0..1 : warp col block (32 cols)

    int it      = blockIdx.x >> 1;
    int jhalf   = blockIdx.x & 1;
    int rowBase = it * BM;
    int jBase0  = jhalf * (NN / JHALVES);

    int*   sTG = (int*)(smem + SM_TG);
    float* sCN = (float*)(smem + SM_CN);
    float* Cs  = (float*)(smem + SM_C);

    // ---- prologue: stage tg/cn for the whole j-half ----
#pragma unroll
    for (int t = tid; t < NN / JHALVES; t += 256) {
        sTG[t] = tgt[jBase0 + t];
        sCN[t] = g_cn[jBase0 + t];
    }
    // ---- A hi+lo: 4096 16B chunks ----
#pragma unroll 4
    for (int itc = 0; itc < 16; itc++) {
        int q   = itc * 256 + tid;
        int m   = q >> 11;
        int q2  = q & 2047;
        int row = q2 >> 4;
        int c   = q2 & 15;
        const __nv_bfloat16* g = (m ? g_lo : g_hi) + (size_t)(rowBase + row) * DD + c * 8;
        cp16(smb + (m ? SM_AL : SM_AH) + row * ASTRIDE + c * 16, g);
    }
    // ---- B tile 0: 2048 chunks ----
#pragma unroll 4
    for (int itc = 0; itc < 8; itc++) {
        int q   = itc * 256 + tid;
        int m   = q >> 10;
        int q2  = q & 1023;
        int row = q2 >> 4;
        int c   = q2 & 15;
        const __nv_bfloat16* g = (m ? g_lo : g_hi) + (size_t)(jBase0 + row) * DD + c * 8;
        cp16(smb + SM_B + m * SM_BLO + row * ASTRIDE + c * 16, g);
    }
    CP_COMMIT();

    // per-row state (threads 0..127 own rows)
    int   iglob = rowBase + (tid & 127);
    float rni   = g_rn[iglob];
    int   tgi   = tgt[iglob];
    float t5[KNN];
#pragma unroll
    for (int k = 0; k < KNN; k++) t5[k] = FLT_MAX;
    float th = FLT_MAX;

    // ldmatrix base addresses
    uint32_t aOffH = smb + SM_AH + (wm * 32 + (lane & 15)) * ASTRIDE + (lane >> 4) * 16;
    uint32_t aOffL = aOffH + (SM_AL - SM_AH);
    uint32_t bRow  = (wn * 32 + (lane & 7)) * ASTRIDE + ((lane >> 3) & 1) * 16;

    for (int u = 0; u < JTILES; u++) {
        __syncthreads();              // all warps done with prior tile's mma + scan
        // prefetch B(u+1)
        if (u + 1 < JTILES) {
            int jb = jBase0 + (u + 1) * BN;
            uint32_t bs = smb + SM_B + ((u + 1) & 1) * SM_BSTG;
#pragma unroll 4
            for (int itc = 0; itc < 8; itc++) {
                int q   = itc * 256 + tid;
                int m   = q >> 10;
                int q2  = q & 1023;
                int row = q2 >> 4;
                int c   = q2 & 15;
                const __nv_bfloat16* g = (m ? g_lo : g_hi) + (size_t)(jb + row) * DD + c * 8;
                cp16(bs + m * SM_BLO + row * ASTRIDE + c * 16, g);
            }
        }
        CP_COMMIT();
        CP_WAIT1();                   // B(u) (and A) resident
        __syncthreads();

        // ---- MMA: acc = Ah*Bh + Al*Bh + Ah*Bl over K=128 ----
        float acc[2][4][4];
#pragma unroll
        for (int mi = 0; mi < 2; mi++)
#pragma unroll
            for (int ni = 0; ni < 4; ni++)
#pragma unroll
                for (int q = 0; q < 4; q++) acc[mi][ni][q] = 0.f;

        uint32_t bH = smb + SM_B + (u & 1) * SM_BSTG + bRow;
        uint32_t bL = bH + SM_BLO;

#pragma unroll
        for (int kk = 0; kk < 8; kk++) {
            uint32_t ah[2][4], al[2][4], bh[4][2], bl[4][2];
#pragma unroll
            for (int mi = 0; mi < 2; mi++) {
                ldsm4(ah[mi], aOffH + mi * 16 * ASTRIDE + kk * 32);
                ldsm4(al[mi], aOffL + mi * 16 * ASTRIDE + kk * 32);
            }
#pragma unroll
            for (int ni = 0; ni < 4; ni++) {
                ldsm2(bh[ni], bH + ni * 8 * ASTRIDE + kk * 32);
                ldsm2(bl[ni], bL + ni * 8 * ASTRIDE + kk * 32);
            }
#pragma unroll
            for (int mi = 0; mi < 2; mi++)
#pragma unroll
                for (int ni = 0; ni < 4; ni++) {
                    mma_bf16(acc[mi][ni], ah[mi], bh[ni]);
                    mma_bf16(acc[mi][ni], al[mi], bh[ni]);
                    mma_bf16(acc[mi][ni], ah[mi], bl[ni]);
                }
        }

        // ---- stage C ----
#pragma unroll
        for (int mi = 0; mi < 2; mi++) {
            int r0 = wm * 32 + mi * 16 + (lane >> 2);
#pragma unroll
            for (int ni = 0; ni < 4; ni++) {
                int col = wn * 32 + ni * 8 + 2 * (lane & 3);
                *reinterpret_cast<float2*>(&Cs[r0 * CSTRIDE + col]) =
                    make_float2(acc[mi][ni][0], acc[mi][ni][1]);
                *reinterpret_cast<float2*>(&Cs[(r0 + 8) * CSTRIDE + col]) =
                    make_float2(acc[mi][ni][2], acc[mi][ni][3]);
            }
        }
        __syncthreads();

        // ---- streaming top-5 over this tile's 64 columns ----
        if (tid < BM) {
            const float* crow = &Cs[tid * CSTRIDE];
            int jb = u * BN;
#pragma unroll 4
            for (int jj = 0; jj < BN; jj++) {
                float d2 = fmaf(-2.0f, crow[jj], rni + sCN[jb + jj]);
                if (d2 < th && sTG[jb + jj] == tgi && (jBase0 + jb + jj) != iglob) {
                    int mi = 0; float mv = t5[0];
#pragma unroll
                    for (int k = 1; k < KNN; k++) if (t5[k] > mv) { mv = t5[k]; mi = k; }
#pragma unroll
                    for (int k = 0; k < KNN; k++) if (k == mi) t5[k] = d2;
                    th = t5[0];
#pragma unroll
                    for (int k = 1; k < KNN; k++) th = fmaxf(th, t5[k]);
                }
            }
        }
    }

    if (tid < BM) {
#pragma unroll
        for (int k = 0; k < KNN; k++) g_part5[jhalf][iglob][k] = t5[k];
    }
}

// ---------------- merge + pair sum ----------------
__global__ void k_merge() {
    int i = blockIdx.x * blockDim.x + threadIdx.x;
    float v[JHALVES * KNN];
#pragma unroll
    for (int sp = 0; sp < JHALVES; sp++)
#pragma unroll
        for (int k = 0; k < KNN; k++) v[sp * KNN + k] = g_part5[sp][i][k];

    float sum = 0.f;
#pragma unroll
    for (int sel = 0; sel < KNN; sel++) {
        float mv = v[0]; int mi = 0;
#pragma unroll
        for (int k = 1; k < JHALVES * KNN; k++)
            if (v[k] < mv) { mv = v[k]; mi = k; }
        if (mv < 1e37f) sum += mv;
#pragma unroll
        for (int k = 0; k < JHALVES * KNN; k++)
            if (k == mi) v[k] = FLT_MAX;
    }

    __shared__ double sh[256];
    sh[threadIdx.x] = (double)sum / (double)DD;
    __syncthreads();
#pragma unroll
    for (int o = 128; o > 0; o >>= 1) {
        if (threadIdx.x < o) sh[threadIdx.x] += sh[threadIdx.x + o];
        __syncthreads();
    }
    if (threadIdx.x == 0) atomicAdd(&g_accPair, sh[0]);
}

__global__ void k_final(float* out) {
    out[0] = (float)(g_accCE / (double)NN + (0.5 / (double)KNN) * g_accPair);
}

// ---------------- launch ----------------
extern "C" void kernel_launch(void* const* d_in, const int* in_sizes, int n_in,
                              void* d_out, int out_size) {
    const float* x  = nullptr;
    const float* sc = nullptr;
    const int*   tg = nullptr;
    for (int i = 0; i < n_in; i++) {
        if (in_sizes[i] == NN * DD)      x  = (const float*)d_in[i];
        else if (in_sizes[i] == NN * CC) sc = (const float*)d_in[i];
        else if (in_sizes[i] == NN)      tg = (const int*)d_in[i];
    }
    float* out = (float*)d_out;

    cudaFuncSetAttribute(k_dist, cudaFuncAttributeMaxDynamicSharedMemorySize, SM_TOTAL);

    k_init<<<1, 1>>>();
    k_convert<<<NN * DD / 4 / 256, 256>>>(x);
    k_norms<<<NN / 8, 256>>>(x);
    k_ce<<<NN / 256, 256>>>(sc, tg);
    k_dist<<<ITILES * JHALVES, 256, SM_TOTAL>>>(tg);
    k_merge<<<NN / 256, 256>>>();
    k_final<<<1, 1>>>(out);
}

// round 4
// speedup vs baseline: 4.1480x; 1.6260x over previous
#include <cuda_runtime.h>
#include <cuda_bf16.h>
#include <float.h>
#include <math.h>
#include <stdint.h>

#define NN 8192
#define DD 128
#define CC 7
#define KNN 5
#define EPSF 1e-6f

#define BM 128
#define BN 128
#define THREADS 512
#define JHALVES 2
#define JTILES (NN / JHALVES / BN)     // 32 j-tiles per CTA
#define ITILES (NN / BM)               // 64 i-tiles

#define ASTRIDE 272                    // 128 bf16 = 256B + 16B pad
#define CSTRIDE 132                    // floats

// ---------------- smem map (bytes) ----------------
#define SM_TG   0                       // int  [2][128]
#define SM_CN   1024                    // float[2][128]
#define SM_AH   2048                    // 128 * 272
#define SM_AL   36864
#define SM_B    71680                   // 2 stages * 34816 (hi only)
#define SM_BSTG 34816
#define SM_C    141312                  // 128 * 132 * 4
#define SM_TOTAL 208896

// ---------------- device scratch ----------------
__device__ __nv_bfloat16 g_hi[NN * DD];
__device__ __nv_bfloat16 g_lo[NN * DD];
__device__ float  g_rn[NN];
__device__ float  g_cn[NN];
__device__ float  g_part5[JHALVES * 4][NN][KNN];
__device__ double g_accCE;
__device__ double g_accPair;

// ---------------- PTX helpers ----------------
__device__ __forceinline__ uint32_t smem_u32(const void* p) {
    uint32_t a;
    asm("{ .reg .u64 t; cvta.to.shared.u64 t, %1; cvt.u32.u64 %0, t; }" : "=r"(a) : "l"(p));
    return a;
}
__device__ __forceinline__ void cp16(uint32_t s, const void* g) {
    asm volatile("cp.async.cg.shared.global [%0], [%1], 16;" :: "r"(s), "l"(g));
}
#define CP_COMMIT() asm volatile("cp.async.commit_group;" ::: "memory")
#define CP_WAIT1()  asm volatile("cp.async.wait_group 1;" ::: "memory")

__device__ __forceinline__ void ldsm4(uint32_t* r, uint32_t a) {
    asm volatile("ldmatrix.sync.aligned.m8n8.x4.shared.b16 {%0,%1,%2,%3}, [%4];"
                 : "=r"(r[0]), "=r"(r[1]), "=r"(r[2]), "=r"(r[3]) : "r"(a));
}
__device__ __forceinline__ void ldsm2(uint32_t* r, uint32_t a) {
    asm volatile("ldmatrix.sync.aligned.m8n8.x2.shared.b16 {%0,%1}, [%2];"
                 : "=r"(r[0]), "=r"(r[1]) : "r"(a));
}
__device__ __forceinline__ void mma_bf16(float* c, const uint32_t* a, const uint32_t* b) {
    asm volatile("mma.sync.aligned.m16n8k16.row.col.f32.bf16.bf16.f32 "
                 "{%0,%1,%2,%3}, {%4,%5,%6,%7}, {%8,%9}, {%0,%1,%2,%3};"
                 : "+f"(c[0]), "+f"(c[1]), "+f"(c[2]), "+f"(c[3])
                 : "r"(a[0]), "r"(a[1]), "r"(a[2]), "r"(a[3]), "r"(b[0]), "r"(b[1]));
}

// ---------------- small kernels ----------------
__global__ void k_init() { g_accCE = 0.0; g_accPair = 0.0; }

__global__ void k_convert(const float* __restrict__ x) {
    int idx = blockIdx.x * blockDim.x + threadIdx.x;
    float4 v = reinterpret_cast<const float4*>(x)[idx];
    __nv_bfloat16 h0 = __float2bfloat16(v.x), h1 = __float2bfloat16(v.y);
    __nv_bfloat16 h2 = __float2bfloat16(v.z), h3 = __float2bfloat16(v.w);
    __nv_bfloat162 hh0 = {h0, h1}, hh1 = {h2, h3};
    __nv_bfloat162 ll0 = {__float2bfloat16(v.x - __bfloat162float(h0)),
                          __float2bfloat16(v.y - __bfloat162float(h1))};
    __nv_bfloat162 ll1 = {__float2bfloat16(v.z - __bfloat162float(h2)),
                          __float2bfloat16(v.w - __bfloat162float(h3))};
    reinterpret_cast<__nv_bfloat162*>(g_hi)[idx * 2]     = hh0;
    reinterpret_cast<__nv_bfloat162*>(g_hi)[idx * 2 + 1] = hh1;
    reinterpret_cast<__nv_bfloat162*>(g_lo)[idx * 2]     = ll0;
    reinterpret_cast<__nv_bfloat162*>(g_lo)[idx * 2 + 1] = ll1;
}

__global__ void k_norms(const float* __restrict__ x) {
    int row  = blockIdx.x * 8 + (threadIdx.x >> 5);
    int lane = threadIdx.x & 31;
    float4 v = reinterpret_cast<const float4*>(x + (size_t)row * DD)[lane];
    float s  = v.x + v.y + v.z + v.w;
    float n2 = v.x * v.x + v.y * v.y + v.z * v.z + v.w * v.w;
#pragma unroll
    for (int o = 16; o > 0; o >>= 1) {
        s  += __shfl_xor_sync(0xffffffffu, s, o);
        n2 += __shfl_xor_sync(0xffffffffu, n2, o);
    }
    if (lane == 0) {
        g_rn[row] = n2 + 2.0f * EPSF * s + (float)DD * EPSF * EPSF;
        g_cn[row] = n2 - 2.0f * EPSF * s;
    }
}

__global__ void k_ce(const float* __restrict__ sc, const int* __restrict__ tg) {
    int i = blockIdx.x * blockDim.x + threadIdx.x;
    const float* s = sc + (size_t)i * CC;
    float m = s[0];
#pragma unroll
    for (int c = 1; c < CC; c++) m = fmaxf(m, s[c]);
    float sum = 0.f;
#pragma unroll
    for (int c = 0; c < CC; c++) sum += expf(s[c] - m);
    float ce = m + logf(sum) - s[tg[i]];

    __shared__ double sh[128];
    sh[threadIdx.x] = (double)ce;
    __syncthreads();
#pragma unroll
    for (int o = 64; o > 0; o >>= 1) {
        if (threadIdx.x < o) sh[threadIdx.x] += sh[threadIdx.x + o];
        __syncthreads();
    }
    if (threadIdx.x == 0) atomicAdd(&g_accCE, sh[0]);
}

// ---------------- fused bf16 mma.sync GEMM + streaming top-5 ----------------
__global__ void __launch_bounds__(THREADS, 1)
k_dist(const int* __restrict__ tgt) {
    extern __shared__ char smem[];
    uint32_t smb = smem_u32(smem);
    int tid  = threadIdx.x;
    int lane = tid & 31;
    int w    = tid >> 5;
    int wm   = w >> 2;          // 0..3 : 32-row block
    int wn   = w & 3;           // 0..3 : 32-col block

    int it      = blockIdx.x >> 1;
    int jhalf   = blockIdx.x & 1;
    int rowBase = it * BM;
    int jBase0  = jhalf * (NN / JHALVES);

    int*   sTG = (int*)(smem + SM_TG);     // [2][128]
    float* sCN = (float*)(smem + SM_CN);   // [2][128]
    float* Cs  = (float*)(smem + SM_C);

    // ---- prologue: A hi+lo (4096 chunks) ----
#pragma unroll
    for (int itc = 0; itc < 8; itc++) {
        int q   = itc * THREADS + tid;
        int m   = q >> 11;
        int q2  = q & 2047;
        int row = q2 >> 4;
        int c   = q2 & 15;
        const __nv_bfloat16* g = (m ? g_lo : g_hi) + (size_t)(rowBase + row) * DD + c * 8;
        cp16(smb + (m ? SM_AL : SM_AH) + row * ASTRIDE + c * 16, g);
    }
    // ---- B tile 0 (hi only, 2048 chunks) ----
#pragma unroll
    for (int itc = 0; itc < 4; itc++) {
        int q   = itc * THREADS + tid;
        int row = q >> 4;
        int c   = q & 15;
        cp16(smb + SM_B + row * ASTRIDE + c * 16,
             g_hi + (size_t)(jBase0 + row) * DD + c * 8);
    }
    CP_COMMIT();
    if (tid < BN) {
        sTG[tid] = tgt[jBase0 + tid];
        sCN[tid] = g_cn[jBase0 + tid];
    }

    // per-row scanner state: 4 threads per row
    int   srow  = tid >> 2;      // 0..127
    int   quad  = tid & 3;       // 0..3
    int   iglob = rowBase + srow;
    float rni   = g_rn[iglob];
    int   tgi   = tgt[iglob];
    float t5[KNN];
#pragma unroll
    for (int k = 0; k < KNN; k++) t5[k] = FLT_MAX;
    float th = FLT_MAX;

    // ldmatrix base addresses
    uint32_t aOffH = smb + SM_AH + (wm * 32 + (lane & 15)) * ASTRIDE + (lane >> 4) * 16;
    uint32_t aOffL = aOffH + (SM_AL - SM_AH);
    uint32_t bRow  = (wn * 32 + (lane & 7)) * ASTRIDE + ((lane >> 3) & 1) * 16;

    for (int u = 0; u < JTILES; u++) {
        __syncthreads();              // prior tile scan done (frees tg/cn slot + C)
        // prefetch B(u+1) hi + tg/cn slot
        if (u + 1 < JTILES) {
            int jb = jBase0 + (u + 1) * BN;
            uint32_t bs = smb + SM_B + ((u + 1) & 1) * SM_BSTG;
#pragma unroll
            for (int itc = 0; itc < 4; itc++) {
                int q   = itc * THREADS + tid;
                int row = q >> 4;
                int c   = q & 15;
                cp16(bs + row * ASTRIDE + c * 16,
                     g_hi + (size_t)(jb + row) * DD + c * 8);
            }
            if (tid < BN) {
                int slot = (u + 1) & 1;
                sTG[slot * BN + tid] = tgt[jb + tid];
                sCN[slot * BN + tid] = g_cn[jb + tid];
            }
        }
        CP_COMMIT();
        CP_WAIT1();                   // B(u) (and A) resident
        __syncthreads();

        // ---- MMA: acc = Ah*Bh + Al*Bh over K=128 ----
        float acc[2][4][4];
#pragma unroll
        for (int mi = 0; mi < 2; mi++)
#pragma unroll
            for (int ni = 0; ni < 4; ni++)
#pragma unroll
                for (int q = 0; q < 4; q++) acc[mi][ni][q] = 0.f;

        uint32_t bH = smb + SM_B + (u & 1) * SM_BSTG + bRow;

#pragma unroll
        for (int kk = 0; kk < 8; kk++) {
            uint32_t ah[2][4], al[2][4], bh[4][2];
#pragma unroll
            for (int mi = 0; mi < 2; mi++) {
                ldsm4(ah[mi], aOffH + mi * 16 * ASTRIDE + kk * 32);
                ldsm4(al[mi], aOffL + mi * 16 * ASTRIDE + kk * 32);
            }
#pragma unroll
            for (int ni = 0; ni < 4; ni++)
                ldsm2(bh[ni], bH + ni * 8 * ASTRIDE + kk * 32);
#pragma unroll
            for (int mi = 0; mi < 2; mi++)
#pragma unroll
                for (int ni = 0; ni < 4; ni++) {
                    mma_bf16(acc[mi][ni], ah[mi], bh[ni]);
                    mma_bf16(acc[mi][ni], al[mi], bh[ni]);
                }
        }

        // ---- stage C ----
#pragma unroll
        for (int mi = 0; mi < 2; mi++) {
            int r0 = wm * 32 + mi * 16 + (lane >> 2);
#pragma unroll
            for (int ni = 0; ni < 4; ni++) {
                int col = wn * 32 + ni * 8 + 2 * (lane & 3);
                *reinterpret_cast<float2*>(&Cs[r0 * CSTRIDE + col]) =
                    make_float2(acc[mi][ni][0], acc[mi][ni][1]);
                *reinterpret_cast<float2*>(&Cs[(r0 + 8) * CSTRIDE + col]) =
                    make_float2(acc[mi][ni][2], acc[mi][ni][3]);
            }
        }
        __syncthreads();

        // ---- streaming top-5: 4 scanners/row, 32 cols each, skewed (bank-free) ----
        {
            int slot = (u & 1) * BN;
            int jbg  = jBase0 + u * BN;
            const float* crow = &Cs[srow * CSTRIDE + quad * 32];
            const float* cns  = &sCN[slot + quad * 32];
            const int*   tgs  = &sTG[slot + quad * 32];
#pragma unroll 4
            for (int jj = 0; jj < 32; jj++) {
                int p  = (jj + quad) & 31;
                float d2 = fmaf(-2.0f, crow[p], rni + cns[p]);
                if (d2 < th && tgs[p] == tgi && (jbg + quad * 32 + p) != iglob) {
                    int mi = 0; float mv = t5[0];
#pragma unroll
                    for (int k = 1; k < KNN; k++) if (t5[k] > mv) { mv = t5[k]; mi = k; }
#pragma unroll
                    for (int k = 0; k < KNN; k++) if (k == mi) t5[k] = d2;
                    th = t5[0];
#pragma unroll
                    for (int k = 1; k < KNN; k++) th = fmaxf(th, t5[k]);
                }
            }
        }
    }

#pragma unroll
    for (int k = 0; k < KNN; k++) g_part5[jhalf * 4 + quad][iglob][k] = t5[k];
}

// ---------------- merge + pair sum ----------------
__global__ void k_merge() {
    int i = blockIdx.x * blockDim.x + threadIdx.x;
    float v[JHALVES * 4 * KNN];
#pragma unroll
    for (int sp = 0; sp < JHALVES * 4; sp++)
#pragma unroll
        for (int k = 0; k < KNN; k++) v[sp * KNN + k] = g_part5[sp][i][k];

    float sum = 0.f;
#pragma unroll
    for (int sel = 0; sel < KNN; sel++) {
        float mv = v[0]; int mi = 0;
#pragma unroll
        for (int k = 1; k < JHALVES * 4 * KNN; k++)
            if (v[k] < mv) { mv = v[k]; mi = k; }
        if (mv < 1e37f) sum += mv;
#pragma unroll
        for (int k = 0; k < JHALVES * 4 * KNN; k++)
            if (k == mi) v[k] = FLT_MAX;
    }

    __shared__ double sh[256];
    sh[threadIdx.x] = (double)sum / (double)DD;
    __syncthreads();
#pragma unroll
    for (int o = 128; o > 0; o >>= 1) {
        if (threadIdx.x < o) sh[threadIdx.x] += sh[threadIdx.x + o];
        __syncthreads();
    }
    if (threadIdx.x == 0) atomicAdd(&g_accPair, sh[0]);
}

__global__ void k_final(float* out) {
    out[0] = (float)(g_accCE / (double)NN + (0.5 / (double)KNN) * g_accPair);
}

// ---------------- launch ----------------
extern "C" void kernel_launch(void* const* d_in, const int* in_sizes, int n_in,
                              void* d_out, int out_size) {
    const float* x  = nullptr;
    const float* sc = nullptr;
    const int*   tg = nullptr;
    for (int i = 0; i < n_in; i++) {
        if (in_sizes[i] == NN * DD)      x  = (const float*)d_in[i];
        else if (in_sizes[i] == NN * CC) sc = (const float*)d_in[i];
        else if (in_sizes[i] == NN)      tg = (const int*)d_in[i];
    }
    float* out = (float*)d_out;

    cudaFuncSetAttribute(k_dist, cudaFuncAttributeMaxDynamicSharedMemorySize, SM_TOTAL);

    k_init<<<1, 1>>>();
    k_convert<<<NN * DD / 4 / 256, 256>>>(x);
    k_norms<<<NN / 8, 256>>>(x);
    k_ce<<<NN / 128, 128>>>(sc, tg);
    k_dist<<<ITILES * JHALVES, THREADS, SM_TOTAL>>>(tg);
    k_merge<<<NN / 256, 256>>>();
    k_final<<<1, 1>>>(out);
}

// round 5
// speedup vs baseline: 4.7666x; 1.1491x over previous
#include <cuda_runtime.h>
#include <cuda_bf16.h>
#include <float.h>
#include <math.h>
#include <stdint.h>

#define NN 8192
#define DD 128
#define CC 7
#define KNN 5
#define EPSF 1e-6f

#define BM 128
#define BN 128
#define THREADS 512
#define JHALVES 2
#define JTILES (NN / JHALVES / BN)     // 32 j-tiles per CTA
#define ITILES (NN / BM)               // 64 i-tiles

#define ASTRIDE 272                    // 128 bf16 = 256B + 16B pad
#define CSTRIDE 132                    // floats

// ---------------- smem map (bytes) ----------------
#define SM_TG   0                       // int  [2][128]
#define SM_CN   1024                    // float[2][128]
#define SM_A    2048                    // 128 * 272 = 34816
#define SM_B    36864                   // 2 stages * 34816
#define SM_BSTG 34816
#define SM_C    106496                  // 128 * 132 * 4 = 67584
#define SM_TOTAL 174080

// ---------------- device scratch ----------------
__device__ __nv_bfloat16 g_hi[NN * DD];
__device__ float  g_rn[NN];
__device__ float  g_cn[NN];
__device__ float  g_part5[JHALVES * 4][NN][KNN];
__device__ double g_accCE;
__device__ double g_accPair;

// ---------------- PTX helpers ----------------
__device__ __forceinline__ uint32_t smem_u32(const void* p) {
    uint32_t a;
    asm("{ .reg .u64 t; cvta.to.shared.u64 t, %1; cvt.u32.u64 %0, t; }" : "=r"(a) : "l"(p));
    return a;
}
__device__ __forceinline__ void cp16(uint32_t s, const void* g) {
    asm volatile("cp.async.cg.shared.global [%0], [%1], 16;" :: "r"(s), "l"(g));
}
#define CP_COMMIT() asm volatile("cp.async.commit_group;" ::: "memory")
#define CP_WAIT1()  asm volatile("cp.async.wait_group 1;" ::: "memory")

__device__ __forceinline__ void ldsm4(uint32_t* r, uint32_t a) {
    asm volatile("ldmatrix.sync.aligned.m8n8.x4.shared.b16 {%0,%1,%2,%3}, [%4];"
                 : "=r"(r[0]), "=r"(r[1]), "=r"(r[2]), "=r"(r[3]) : "r"(a));
}
__device__ __forceinline__ void ldsm2(uint32_t* r, uint32_t a) {
    asm volatile("ldmatrix.sync.aligned.m8n8.x2.shared.b16 {%0,%1}, [%2];"
                 : "=r"(r[0]), "=r"(r[1]) : "r"(a));
}
__device__ __forceinline__ void mma_bf16(float* c, const uint32_t* a, const uint32_t* b) {
    asm volatile("mma.sync.aligned.m16n8k16.row.col.f32.bf16.bf16.f32 "
                 "{%0,%1,%2,%3}, {%4,%5,%6,%7}, {%8,%9}, {%0,%1,%2,%3};"
                 : "+f"(c[0]), "+f"(c[1]), "+f"(c[2]), "+f"(c[3])
                 : "r"(a[0]), "r"(a[1]), "r"(a[2]), "r"(a[3]), "r"(b[0]), "r"(b[1]));
}

// ---------------- small kernels ----------------
__global__ void k_init() { g_accCE = 0.0; g_accPair = 0.0; }

__global__ void k_convert(const float* __restrict__ x) {
    int idx = blockIdx.x * blockDim.x + threadIdx.x;     // NN*DD/4 threads
    float4 v = reinterpret_cast<const float4*>(x)[idx];
    __nv_bfloat162 hh0 = {__float2bfloat16(v.x), __float2bfloat16(v.y)};
    __nv_bfloat162 hh1 = {__float2bfloat16(v.z), __float2bfloat16(v.w)};
    reinterpret_cast<__nv_bfloat162*>(g_hi)[idx * 2]     = hh0;
    reinterpret_cast<__nv_bfloat162*>(g_hi)[idx * 2 + 1] = hh1;
}

__global__ void k_norms(const float* __restrict__ x) {
    int row  = blockIdx.x * 8 + (threadIdx.x >> 5);
    int lane = threadIdx.x & 31;
    float4 v = reinterpret_cast<const float4*>(x + (size_t)row * DD)[lane];
    float s  = v.x + v.y + v.z + v.w;
    float n2 = v.x * v.x + v.y * v.y + v.z * v.z + v.w * v.w;
#pragma unroll
    for (int o = 16; o > 0; o >>= 1) {
        s  += __shfl_xor_sync(0xffffffffu, s, o);
        n2 += __shfl_xor_sync(0xffffffffu, n2, o);
    }
    if (lane == 0) {
        g_rn[row] = n2 + 2.0f * EPSF * s + (float)DD * EPSF * EPSF;
        g_cn[row] = n2 - 2.0f * EPSF * s;
    }
}

__global__ void k_ce(const float* __restrict__ sc, const int* __restrict__ tg) {
    int i = blockIdx.x * blockDim.x + threadIdx.x;
    const float* s = sc + (size_t)i * CC;
    float m = s[0];
#pragma unroll
    for (int c = 1; c < CC; c++) m = fmaxf(m, s[c]);
    float sum = 0.f;
#pragma unroll
    for (int c = 0; c < CC; c++) sum += expf(s[c] - m);
    float ce = m + logf(sum) - s[tg[i]];

    __shared__ double sh[128];
    sh[threadIdx.x] = (double)ce;
    __syncthreads();
#pragma unroll
    for (int o = 64; o > 0; o >>= 1) {
        if (threadIdx.x < o) sh[threadIdx.x] += sh[threadIdx.x + o];
        __syncthreads();
    }
    if (threadIdx.x == 0) atomicAdd(&g_accCE, sh[0]);
}

// ---------------- fused bf16 mma.sync GEMM + streaming top-5 ----------------
__global__ void __launch_bounds__(THREADS, 1)
k_dist(const int* __restrict__ tgt) {
    extern __shared__ char smem[];
    uint32_t smb = smem_u32(smem);
    int tid  = threadIdx.x;
    int lane = tid & 31;
    int w    = tid >> 5;
    int wm   = w >> 2;          // 0..3 : 32-row block
    int wn   = w & 3;           // 0..3 : 32-col block

    int it      = blockIdx.x >> 1;
    int jhalf   = blockIdx.x & 1;
    int rowBase = it * BM;
    int jBase0  = jhalf * (NN / JHALVES);

    int*   sTG = (int*)(smem + SM_TG);     // [2][128]
    float* sCN = (float*)(smem + SM_CN);   // [2][128]
    float* Cs  = (float*)(smem + SM_C);

    // ---- prologue: A (2048 chunks) ----
#pragma unroll
    for (int itc = 0; itc < 4; itc++) {
        int q   = itc * THREADS + tid;
        int row = q >> 4;
        int c   = q & 15;
        cp16(smb + SM_A + row * ASTRIDE + c * 16,
             g_hi + (size_t)(rowBase + row) * DD + c * 8);
    }
    // ---- B tile 0 (2048 chunks) ----
#pragma unroll
    for (int itc = 0; itc < 4; itc++) {
        int q   = itc * THREADS + tid;
        int row = q >> 4;
        int c   = q & 15;
        cp16(smb + SM_B + row * ASTRIDE + c * 16,
             g_hi + (size_t)(jBase0 + row) * DD + c * 8);
    }
    CP_COMMIT();
    if (tid < BN) {
        sTG[tid] = tgt[jBase0 + tid];
        sCN[tid] = g_cn[jBase0 + tid];
    }

    // per-row scanner state: 4 threads per row
    int   srow  = tid >> 2;      // 0..127
    int   quad  = tid & 3;       // 0..3
    int   iglob = rowBase + srow;
    float rni   = g_rn[iglob];
    int   tgi   = tgt[iglob];
    float t5[KNN];
#pragma unroll
    for (int k = 0; k < KNN; k++) t5[k] = FLT_MAX;
    float th = FLT_MAX;

    // ldmatrix base addresses
    uint32_t aOff = smb + SM_A + (wm * 32 + (lane & 15)) * ASTRIDE + (lane >> 4) * 16;
    uint32_t bRow = (wn * 32 + (lane & 7)) * ASTRIDE + ((lane >> 3) & 1) * 16;

    for (int u = 0; u < JTILES; u++) {
        __syncthreads();              // prior tile scan done (frees tg/cn slot + C)
        // prefetch B(u+1) + tg/cn slot
        if (u + 1 < JTILES) {
            int jb = jBase0 + (u + 1) * BN;
            uint32_t bs = smb + SM_B + ((u + 1) & 1) * SM_BSTG;
#pragma unroll
            for (int itc = 0; itc < 4; itc++) {
                int q   = itc * THREADS + tid;
                int row = q >> 4;
                int c   = q & 15;
                cp16(bs + row * ASTRIDE + c * 16,
                     g_hi + (size_t)(jb + row) * DD + c * 8);
            }
            if (tid < BN) {
                int slot = (u + 1) & 1;
                sTG[slot * BN + tid] = tgt[jb + tid];
                sCN[slot * BN + tid] = g_cn[jb + tid];
            }
        }
        CP_COMMIT();
        CP_WAIT1();                   // B(u) (and A) resident
        __syncthreads();

        // ---- MMA: acc = A*B^T over K=128 ----
        float acc[2][4][4];
#pragma unroll
        for (int mi = 0; mi < 2; mi++)
#pragma unroll
            for (int ni = 0; ni < 4; ni++)
#pragma unroll
                for (int q = 0; q < 4; q++) acc[mi][ni][q] = 0.f;

        uint32_t bH = smb + SM_B + (u & 1) * SM_BSTG + bRow;

#pragma unroll
        for (int kk = 0; kk < 8; kk++) {
            uint32_t ah[2][4], bh[4][2];
#pragma unroll
            for (int mi = 0; mi < 2; mi++)
                ldsm4(ah[mi], aOff + mi * 16 * ASTRIDE + kk * 32);
#pragma unroll
            for (int ni = 0; ni < 4; ni++)
                ldsm2(bh[ni], bH + ni * 8 * ASTRIDE + kk * 32);
#pragma unroll
            for (int mi = 0; mi < 2; mi++)
#pragma unroll
                for (int ni = 0; ni < 4; ni++)
                    mma_bf16(acc[mi][ni], ah[mi], bh[ni]);
        }

        // ---- stage C ----
#pragma unroll
        for (int mi = 0; mi < 2; mi++) {
            int r0 = wm * 32 + mi * 16 + (lane >> 2);
#pragma unroll
            for (int ni = 0; ni < 4; ni++) {
                int col = wn * 32 + ni * 8 + 2 * (lane & 3);
                *reinterpret_cast<float2*>(&Cs[r0 * CSTRIDE + col]) =
                    make_float2(acc[mi][ni][0], acc[mi][ni][1]);
                *reinterpret_cast<float2*>(&Cs[(r0 + 8) * CSTRIDE + col]) =
                    make_float2(acc[mi][ni][2], acc[mi][ni][3]);
            }
        }
        __syncthreads();

        // ---- streaming top-5: 4 scanners/row, 32 cols each, skewed ----
        {
            int slot = (u & 1) * BN;
            int jbg  = jBase0 + u * BN;
            const float* crow = &Cs[srow * CSTRIDE + quad * 32];
            const float* cns  = &sCN[slot + quad * 32];
            const int*   tgs  = &sTG[slot + quad * 32];
#pragma unroll 4
            for (int jj = 0; jj < 32; jj++) {
                int p  = (jj + quad) & 31;
                float d2 = fmaf(-2.0f, crow[p], rni + cns[p]);
                if (d2 < th && tgs[p] == tgi && (jbg + quad * 32 + p) != iglob) {
                    int mi = 0; float mv = t5[0];
#pragma unroll
                    for (int k = 1; k < KNN; k++) if (t5[k] > mv) { mv = t5[k]; mi = k; }
#pragma unroll
                    for (int k = 0; k < KNN; k++) if (k == mi) t5[k] = d2;
                    th = t5[0];
#pragma unroll
                    for (int k = 1; k < KNN; k++) th = fmaxf(th, t5[k]);
                }
            }
        }
    }

#pragma unroll
    for (int k = 0; k < KNN; k++) g_part5[jhalf * 4 + quad][iglob][k] = t5[k];
}

// ---------------- merge + pair sum ----------------
__global__ void k_merge() {
    int i = blockIdx.x * blockDim.x + threadIdx.x;
    float v[JHALVES * 4 * KNN];
#pragma unroll
    for (int sp = 0; sp < JHALVES * 4; sp++)
#pragma unroll
        for (int k = 0; k < KNN; k++) v[sp * KNN + k] = g_part5[sp][i][k];

    float sum = 0.f;
#pragma unroll
    for (int sel = 0; sel < KNN; sel++) {
        float mv = v[0]; int mi = 0;
#pragma unroll
        for (int k = 1; k < JHALVES * 4 * KNN; k++)
            if (v[k] < mv) { mv = v[k]; mi = k; }
        if (mv < 1e37f) sum += mv;
#pragma unroll
        for (int k = 0; k < JHALVES * 4 * KNN; k++)
            if (k == mi) v[k] = FLT_MAX;
    }

    __shared__ double sh[256];
    sh[threadIdx.x] = (double)sum / (double)DD;
    __syncthreads();
#pragma unroll
    for (int o = 128; o > 0; o >>= 1) {
        if (threadIdx.x < o) sh[threadIdx.x] += sh[threadIdx.x + o];
        __syncthreads();
    }
    if (threadIdx.x == 0) atomicAdd(&g_accPair, sh[0]);
}

__global__ void k_final(float* out) {
    out[0] = (float)(g_accCE / (double)NN + (0.5 / (double)KNN) * g_accPair);
}

// ---------------- launch ----------------
extern "C" void kernel_launch(void* const* d_in, const int* in_sizes, int n_in,
                              void* d_out, int out_size) {
    const float* x  = nullptr;
    const float* sc = nullptr;
    const int*   tg = nullptr;
    for (int i = 0; i < n_in; i++) {
        if (in_sizes[i] == NN * DD)      x  = (const float*)d_in[i];
        else if (in_sizes[i] == NN * CC) sc = (const float*)d_in[i];
        else if (in_sizes[i] == NN)      tg = (const int*)d_in[i];
    }
    float* out = (float*)d_out;

    cudaFuncSetAttribute(k_dist, cudaFuncAttributeMaxDynamicSharedMemorySize, SM_TOTAL);

    k_init<<<1, 1>>>();
    k_convert<<<NN * DD / 4 / 256, 256>>>(x);
    k_norms<<<NN / 8, 256>>>(x);
    k_ce<<<NN / 128, 128>>>(sc, tg);
    k_dist<<<ITILES * JHALVES, THREADS, SM_TOTAL>>>(tg);
    k_merge<<<NN / 256, 256>>>();
    k_final<<<1, 1>>>(out);
}

// round 6
// speedup vs baseline: 5.0292x; 1.0551x over previous
#include <cuda_runtime.h>
#include <cuda_bf16.h>
#include <float.h>
#include <math.h>
#include <stdint.h>

#define NN 8192
#define DD 128
#define CC 7
#define KNN 5
#define EPSF 1e-6f

#define BM 128
#define BN 128
#define THREADS 512
#define JHALVES 2
#define JTILES (NN / JHALVES / BN)     // 32 j-tiles per CTA
#define ITILES (NN / BM)               // 64 i-tiles

#define ASTRIDE 272                    // 128 bf16 = 256B + 16B pad

// ---------------- smem map (bytes) ----------------
#define SM_TG   0                       // int  [2][128]
#define SM_CN   1024                    // float[2][128]
#define SM_A    2048                    // 128 * 272 = 34816
#define SM_B    36864                   // 2 stages * 34816
#define SM_BSTG 34816
#define SM_TOTAL 106496
// final-merge overlay (reuses B region): 128 rows * 16 slots * 5 floats = 40960 B

// ---------------- device scratch ----------------
__device__ __nv_bfloat16 g_hi[NN * DD];
__device__ float  g_rn[NN];
__device__ float  g_cn[NN];
__device__ float  g_part5[JHALVES][NN][KNN];
__device__ double g_accCE;
__device__ double g_accPair;

// ---------------- PTX helpers ----------------
__device__ __forceinline__ uint32_t smem_u32(const void* p) {
    uint32_t a;
    asm("{ .reg .u64 t; cvta.to.shared.u64 t, %1; cvt.u32.u64 %0, t; }" : "=r"(a) : "l"(p));
    return a;
}
__device__ __forceinline__ void cp16(uint32_t s, const void* g) {
    asm volatile("cp.async.cg.shared.global [%0], [%1], 16;" :: "r"(s), "l"(g));
}
#define CP_COMMIT() asm volatile("cp.async.commit_group;" ::: "memory")
#define CP_WAIT1()  asm volatile("cp.async.wait_group 1;" ::: "memory")

__device__ __forceinline__ void ldsm4(uint32_t* r, uint32_t a) {
    asm volatile("ldmatrix.sync.aligned.m8n8.x4.shared.b16 {%0,%1,%2,%3}, [%4];"
                 : "=r"(r[0]), "=r"(r[1]), "=r"(r[2]), "=r"(r[3]) : "r"(a));
}
__device__ __forceinline__ void ldsm2(uint32_t* r, uint32_t a) {
    asm volatile("ldmatrix.sync.aligned.m8n8.x2.shared.b16 {%0,%1}, [%2];"
                 : "=r"(r[0]), "=r"(r[1]) : "r"(a));
}
__device__ __forceinline__ void mma_bf16(float* c, const uint32_t* a, const uint32_t* b) {
    asm volatile("mma.sync.aligned.m16n8k16.row.col.f32.bf16.bf16.f32 "
                 "{%0,%1,%2,%3}, {%4,%5,%6,%7}, {%8,%9}, {%0,%1,%2,%3};"
                 : "+f"(c[0]), "+f"(c[1]), "+f"(c[2]), "+f"(c[3])
                 : "r"(a[0]), "r"(a[1]), "r"(a[2]), "r"(a[3]), "r"(b[0]), "r"(b[1]));
}

// ---------------- small kernels ----------------
__global__ void k_init() { g_accCE = 0.0; g_accPair = 0.0; }

__global__ void k_convert(const float* __restrict__ x) {
    int idx = blockIdx.x * blockDim.x + threadIdx.x;     // NN*DD/4 threads
    float4 v = reinterpret_cast<const float4*>(x)[idx];
    __nv_bfloat162 hh0 = {__float2bfloat16(v.x), __float2bfloat16(v.y)};
    __nv_bfloat162 hh1 = {__float2bfloat16(v.z), __float2bfloat16(v.w)};
    reinterpret_cast<__nv_bfloat162*>(g_hi)[idx * 2]     = hh0;
    reinterpret_cast<__nv_bfloat162*>(g_hi)[idx * 2 + 1] = hh1;
}

__global__ void k_norms(const float* __restrict__ x) {
    int row  = blockIdx.x * 8 + (threadIdx.x >> 5);
    int lane = threadIdx.x & 31;
    float4 v = reinterpret_cast<const float4*>(x + (size_t)row * DD)[lane];
    float s  = v.x + v.y + v.z + v.w;
    float n2 = v.x * v.x + v.y * v.y + v.z * v.z + v.w * v.w;
#pragma unroll
    for (int o = 16; o > 0; o >>= 1) {
        s  += __shfl_xor_sync(0xffffffffu, s, o);
        n2 += __shfl_xor_sync(0xffffffffu, n2, o);
    }
    if (lane == 0) {
        g_rn[row] = n2 + 2.0f * EPSF * s + (float)DD * EPSF * EPSF;
        g_cn[row] = n2 - 2.0f * EPSF * s;
    }
}

__global__ void k_ce(const float* __restrict__ sc, const int* __restrict__ tg) {
    int i = blockIdx.x * blockDim.x + threadIdx.x;
    const float* s = sc + (size_t)i * CC;
    float m = s[0];
#pragma unroll
    for (int c = 1; c < CC; c++) m = fmaxf(m, s[c]);
    float sum = 0.f;
#pragma unroll
    for (int c = 0; c < CC; c++) sum += expf(s[c] - m);
    float ce = m + logf(sum) - s[tg[i]];

    __shared__ double sh[128];
    sh[threadIdx.x] = (double)ce;
    __syncthreads();
#pragma unroll
    for (int o = 64; o > 0; o >>= 1) {
        if (threadIdx.x < o) sh[threadIdx.x] += sh[threadIdx.x + o];
        __syncthreads();
    }
    if (threadIdx.x == 0) atomicAdd(&g_accCE, sh[0]);
}

// ---------------- fused bf16 mma.sync GEMM + register top-5 ----------------
__global__ void __launch_bounds__(THREADS, 1)
k_dist(const int* __restrict__ tgt) {
    extern __shared__ char smem[];
    uint32_t smb = smem_u32(smem);
    int tid  = threadIdx.x;
    int lane = tid & 31;
    int w    = tid >> 5;
    int wm   = w >> 2;          // 0..3 : 32-row block
    int wn   = w & 3;           // 0..3 : 32-col block

    int it      = blockIdx.x >> 1;
    int jhalf   = blockIdx.x & 1;
    int rowBase = it * BM;
    int jBase0  = jhalf * (NN / JHALVES);

    int*   sTG = (int*)(smem + SM_TG);     // [2][128]
    float* sCN = (float*)(smem + SM_CN);   // [2][128]

    // ---- prologue: A (2048 chunks) ----
#pragma unroll
    for (int itc = 0; itc < 4; itc++) {
        int q   = itc * THREADS + tid;
        int row = q >> 4;
        int c   = q & 15;
        cp16(smb + SM_A + row * ASTRIDE + c * 16,
             g_hi + (size_t)(rowBase + row) * DD + c * 8);
    }
    // ---- B tile 0 (2048 chunks) ----
#pragma unroll
    for (int itc = 0; itc < 4; itc++) {
        int q   = itc * THREADS + tid;
        int row = q >> 4;
        int c   = q & 15;
        cp16(smb + SM_B + row * ASTRIDE + c * 16,
             g_hi + (size_t)(jBase0 + row) * DD + c * 8);
    }
    CP_COMMIT();
    if (tid < BN) {
        sTG[tid] = tgt[jBase0 + tid];
        sCN[tid] = g_cn[jBase0 + tid];
    }

    // ---- per-thread row state: the 4 local rows this thread's fragments touch ----
    // local row q: wm*32 + (lane>>2) + 8*(q&1) + 16*(q>>1)
    int   lrow[4];
    float rnq[4];
    int   tgq[4];
#pragma unroll
    for (int q = 0; q < 4; q++) {
        lrow[q] = wm * 32 + (lane >> 2) + ((q & 1) << 3) + ((q >> 1) << 4);
        rnq[q]  = g_rn[rowBase + lrow[q]];
        tgq[q]  = tgt[rowBase + lrow[q]];
    }
    float t5[4][KNN];
    float th[4];
#pragma unroll
    for (int q = 0; q < 4; q++) {
        th[q] = FLT_MAX;
#pragma unroll
        for (int k = 0; k < KNN; k++) t5[q][k] = FLT_MAX;
    }

    // ldmatrix base addresses
    uint32_t aOff = smb + SM_A + (wm * 32 + (lane & 15)) * ASTRIDE + (lane >> 4) * 16;
    uint32_t bRow = (wn * 32 + (lane & 7)) * ASTRIDE + ((lane >> 3) & 1) * 16;

    for (int u = 0; u < JTILES; u++) {
        __syncthreads();              // epilogue(u-1) done: safe to overwrite stage/slots
        if (u + 1 < JTILES) {
            int jb = jBase0 + (u + 1) * BN;
            uint32_t bs = smb + SM_B + ((u + 1) & 1) * SM_BSTG;
#pragma unroll
            for (int itc = 0; itc < 4; itc++) {
                int q   = itc * THREADS + tid;
                int row = q >> 4;
                int c   = q & 15;
                cp16(bs + row * ASTRIDE + c * 16,
                     g_hi + (size_t)(jb + row) * DD + c * 8);
            }
            if (tid < BN) {
                int slot = (u + 1) & 1;
                sTG[slot * BN + tid] = tgt[jb + tid];
                sCN[slot * BN + tid] = g_cn[jb + tid];
            }
        }
        CP_COMMIT();
        CP_WAIT1();                   // B(u) (and A) resident
        __syncthreads();

        // ---- MMA: acc = A*B^T over K=128 ----
        float acc[2][4][4];
#pragma unroll
        for (int mi = 0; mi < 2; mi++)
#pragma unroll
            for (int ni = 0; ni < 4; ni++)
#pragma unroll
                for (int q = 0; q < 4; q++) acc[mi][ni][q] = 0.f;

        uint32_t bH = smb + SM_B + (u & 1) * SM_BSTG + bRow;

#pragma unroll
        for (int kk = 0; kk < 8; kk++) {
            uint32_t ah[2][4], bh[4][2];
#pragma unroll
            for (int mi = 0; mi < 2; mi++)
                ldsm4(ah[mi], aOff + mi * 16 * ASTRIDE + kk * 32);
#pragma unroll
            for (int ni = 0; ni < 4; ni++)
                ldsm2(bh[ni], bH + ni * 8 * ASTRIDE + kk * 32);
#pragma unroll
            for (int mi = 0; mi < 2; mi++)
#pragma unroll
                for (int ni = 0; ni < 4; ni++)
                    mma_bf16(acc[mi][ni], ah[mi], bh[ni]);
        }

        // ---- register epilogue: d2 + top-5 directly on acc ----
        {
            int jb   = jBase0 + u * BN;
            int slot = (u & 1) * BN;
            int sj[4];
#pragma unroll
            for (int q = 0; q < 4; q++) sj[q] = (rowBase + lrow[q]) - jb;  // local col to exclude

#pragma unroll
            for (int ni = 0; ni < 4; ni++) {
                int cb = wn * 32 + ni * 8 + 2 * (lane & 3);
                float cn0 = sCN[slot + cb], cn1 = sCN[slot + cb + 1];
                int   tg0 = sTG[slot + cb], tg1 = sTG[slot + cb + 1];
#pragma unroll
                for (int mi = 0; mi < 2; mi++) {
#pragma unroll
                    for (int h = 0; h < 2; h++) {
                        int q = mi * 2 + h;
                        float d2a = fmaf(-2.0f, acc[mi][ni][2 * h],     rnq[q] + cn0);
                        float d2b = fmaf(-2.0f, acc[mi][ni][2 * h + 1], rnq[q] + cn1);
                        if (d2a < th[q] && tg0 == tgq[q] && cb != sj[q]) {
                            int mix = 0; float mv = t5[q][0];
#pragma unroll
                            for (int k = 1; k < KNN; k++) if (t5[q][k] > mv) { mv = t5[q][k]; mix = k; }
#pragma unroll
                            for (int k = 0; k < KNN; k++) if (k == mix) t5[q][k] = d2a;
                            th[q] = t5[q][0];
#pragma unroll
                            for (int k = 1; k < KNN; k++) th[q] = fmaxf(th[q], t5[q][k]);
                        }
                        if (d2b < th[q] && tg1 == tgq[q] && (cb + 1) != sj[q]) {
                            int mix = 0; float mv = t5[q][0];
#pragma unroll
                            for (int k = 1; k < KNN; k++) if (t5[q][k] > mv) { mv = t5[q][k]; mix = k; }
#pragma unroll
                            for (int k = 0; k < KNN; k++) if (k == mix) t5[q][k] = d2b;
                            th[q] = t5[q][0];
#pragma unroll
                            for (int k = 1; k < KNN; k++) th[q] = fmaxf(th[q], t5[q][k]);
                        }
                    }
                }
            }
        }
    }

    // ---- in-CTA merge: 16 threads per row -> 5 smallest of 80 ----
    __syncthreads();
    float* M = (float*)(smem + SM_B);      // overlay, 40960 B
    int slot16 = wn * 4 + (lane & 3);
#pragma unroll
    for (int q = 0; q < 4; q++)
#pragma unroll
        for (int k = 0; k < KNN; k++)
            M[(lrow[q] * 16 + slot16) * KNN + k] = t5[q][k];
    __syncthreads();

    if (tid < BM) {
        const float* mrow = M + tid * 16 * KNN;
        float best[KNN], bth = FLT_MAX;
#pragma unroll
        for (int k = 0; k < KNN; k++) best[k] = FLT_MAX;
        for (int j = 0; j < 16 * KNN; j++) {
            float v = mrow[j];
            if (v < bth) {
                int mix = 0; float mv = best[0];
#pragma unroll
                for (int k = 1; k < KNN; k++) if (best[k] > mv) { mv = best[k]; mix = k; }
#pragma unroll
                for (int k = 0; k < KNN; k++) if (k == mix) best[k] = v;
                bth = best[0];
#pragma unroll
                for (int k = 1; k < KNN; k++) bth = fmaxf(bth, best[k]);
            }
        }
#pragma unroll
        for (int k = 0; k < KNN; k++) g_part5[jhalf][rowBase + tid][k] = best[k];
    }
}

// ---------------- merge + pair sum ----------------
__global__ void k_merge() {
    int i = blockIdx.x * blockDim.x + threadIdx.x;
    float v[JHALVES * KNN];
#pragma unroll
    for (int sp = 0; sp < JHALVES; sp++)
#pragma unroll
        for (int k = 0; k < KNN; k++) v[sp * KNN + k] = g_part5[sp][i][k];

    float sum = 0.f;
#pragma unroll
    for (int sel = 0; sel < KNN; sel++) {
        float mv = v[0]; int mi = 0;
#pragma unroll
        for (int k = 1; k < JHALVES * KNN; k++)
            if (v[k] < mv) { mv = v[k]; mi = k; }
        if (mv < 1e37f) sum += mv;
#pragma unroll
        for (int k = 0; k < JHALVES * KNN; k++)
            if (k == mi) v[k] = FLT_MAX;
    }

    __shared__ double sh[256];
    sh[threadIdx.x] = (double)sum / (double)DD;
    __syncthreads();
#pragma unroll
    for (int o = 128; o > 0; o >>= 1) {
        if (threadIdx.x < o) sh[threadIdx.x] += sh[threadIdx.x + o];
        __syncthreads();
    }
    if (threadIdx.x == 0) atomicAdd(&g_accPair, sh[0]);
}

__global__ void k_final(float* out) {
    out[0] = (float)(g_accCE / (double)NN + (0.5 / (double)KNN) * g_accPair);
}

// ---------------- launch ----------------
extern "C" void kernel_launch(void* const* d_in, const int* in_sizes, int n_in,
                              void* d_out, int out_size) {
    const float* x  = nullptr;
    const float* sc = nullptr;
    const int*   tg = nullptr;
    for (int i = 0; i < n_in; i++) {
        if (in_sizes[i] == NN * DD)      x  = (const float*)d_in[i];
        else if (in_sizes[i] == NN * CC) sc = (const float*)d_in[i];
        else if (in_sizes[i] == NN)      tg = (const int*)d_in[i];
    }
    float* out = (float*)d_out;

    cudaFuncSetAttribute(k_dist, cudaFuncAttributeMaxDynamicSharedMemorySize, SM_TOTAL);

    k_init<<<1, 1>>>();
    k_convert<<<NN * DD / 4 / 256, 256>>>(x);
    k_norms<<<NN / 8, 256>>>(x);
    k_ce<<<NN / 128, 128>>>(sc, tg);
    k_dist<<<ITILES * JHALVES, THREADS, SM_TOTAL>>>(tg);
    k_merge<<<NN / 256, 256>>>();
    k_final<<<1, 1>>>(out);
}